// round 2
// baseline (speedup 1.0000x reference)
#include <cuda_runtime.h>

#define D_MODEL 1024
#define HID     4096
#define N_KEYS  65536
#define TOPK    6
#define H_CHUNK 128
#define N_HCH   (HID / H_CHUNK)   // 32

// ---- scratch (no allocation allowed) ----
__device__ float g_q[HID];
__device__ float g_vpart[N_HCH * D_MODEL];
__device__ float g_v[D_MODEL];
__device__ float g_c;
__device__ float g_scores[N_KEYS];

// ---------------------------------------------------------------------------
// q[h] = Wq[h,:] . query + bq[h]     (one warp per output row)
// ---------------------------------------------------------------------------
__global__ void k_proj_q(const float* __restrict__ Wq,
                         const float* __restrict__ query,
                         const float* __restrict__ bq) {
    __shared__ float sq[D_MODEL];
    int tid = threadIdx.x;
    for (int i = tid; i < D_MODEL; i += blockDim.x) sq[i] = query[i];
    __syncthreads();

    int warp = tid >> 5, lane = tid & 31;
    int row  = blockIdx.x * 8 + warp;          // grid = HID/8 blocks, 8 warps each

    const float4* W = reinterpret_cast<const float4*>(Wq + (size_t)row * D_MODEL);
    const float4* Q = reinterpret_cast<const float4*>(sq);
    float acc = 0.f;
#pragma unroll
    for (int j = 0; j < 8; j++) {              // 32 lanes * 8 * float4 = 1024 floats
        float4 w = W[lane + 32 * j];
        float4 q = Q[lane + 32 * j];
        acc += w.x * q.x + w.y * q.y + w.z * q.z + w.w * q.w;
    }
#pragma unroll
    for (int off = 16; off; off >>= 1)
        acc += __shfl_down_sync(0xffffffffu, acc, off);
    if (lane == 0) g_q[row] = acc + bq[row];
}

// ---------------------------------------------------------------------------
// v[d] = sum_h Wk[h,d] * q[h]  — partial over h-chunks for parallelism
// grid = (D_MODEL/256, N_HCH), block = 256 ; perfectly coalesced Wk reads
// ---------------------------------------------------------------------------
__global__ void k_vpartial(const float* __restrict__ Wk) {
    int d  = blockIdx.x * 256 + threadIdx.x;
    int h0 = blockIdx.y * H_CHUNK;
    float acc = 0.f;
#pragma unroll 4
    for (int h = 0; h < H_CHUNK; h++)
        acc += Wk[(size_t)(h0 + h) * D_MODEL + d] * g_q[h0 + h];
    g_vpart[blockIdx.y * D_MODEL + d] = acc;
}

// ---------------------------------------------------------------------------
// reduce partials -> v ; block 4 computes c = bk . q
// ---------------------------------------------------------------------------
__global__ void k_vreduce(const float* __restrict__ bk) {
    if (blockIdx.x < 4) {
        int d = blockIdx.x * 256 + threadIdx.x;
        float s = 0.f;
#pragma unroll
        for (int g = 0; g < N_HCH; g++) s += g_vpart[g * D_MODEL + d];
        g_v[d] = s;
    } else {
        __shared__ float red[256];
        float s = 0.f;
        for (int h = threadIdx.x; h < HID; h += 256) s += bk[h] * g_q[h];
        red[threadIdx.x] = s;
        __syncthreads();
        for (int o = 128; o; o >>= 1) {
            if (threadIdx.x < o) red[threadIdx.x] += red[threadIdx.x + o];
            __syncthreads();
        }
        if (threadIdx.x == 0) g_c = red[0];
    }
}

// ---------------------------------------------------------------------------
// scores[n] = key_mat[n,:] . v + c   (one warp per row; 256 MB streamed)
// ---------------------------------------------------------------------------
__global__ void k_scores(const float* __restrict__ key_mat) {
    __shared__ float sv[D_MODEL];
    int tid = threadIdx.x;
    for (int i = tid; i < D_MODEL; i += 256) sv[i] = g_v[i];
    __syncthreads();

    int warp = tid >> 5, lane = tid & 31;
    int row  = blockIdx.x * 8 + warp;          // grid = N_KEYS/8

    const float4* K = reinterpret_cast<const float4*>(key_mat + (size_t)row * D_MODEL);
    const float4* V = reinterpret_cast<const float4*>(sv);
    float acc = 0.f;
#pragma unroll
    for (int j = 0; j < 8; j++) {
        float4 k = K[lane + 32 * j];
        float4 v = V[lane + 32 * j];
        acc += k.x * v.x + k.y * v.y + k.z * v.z + k.w * v.w;
    }
#pragma unroll
    for (int off = 16; off; off >>= 1)
        acc += __shfl_down_sync(0xffffffffu, acc, off);
    if (lane == 0) g_scores[row] = acc + g_c;
}

// ---------------------------------------------------------------------------
// 6 sequential masked argmax passes (exactly the reference loop semantics,
// lower index wins ties), then out = mean of the 6 selected key rows.
// Single block of 1024 threads.
// ---------------------------------------------------------------------------
__global__ void k_topk_mean(const float* __restrict__ key_mat,
                            float* __restrict__ out) {
    __shared__ float sval[1024];
    __shared__ int   sidx[1024];
    __shared__ int   topIdx[TOPK];
    const float NEG_INF = -__int_as_float(0x7f800000);
    int tid = threadIdx.x;

    for (int t = 0; t < TOPK; t++) {
        float best = NEG_INF;
        int   bidx = N_KEYS;
        for (int i = tid; i < N_KEYS; i += 1024) {
            float s = g_scores[i];
            if (s > best) { best = s; bidx = i; }
        }
        sval[tid] = best; sidx[tid] = bidx;
        __syncthreads();
        for (int o = 512; o; o >>= 1) {
            if (tid < o) {
                float v2 = sval[tid + o]; int i2 = sidx[tid + o];
                if (v2 > sval[tid] || (v2 == sval[tid] && i2 < sidx[tid])) {
                    sval[tid] = v2; sidx[tid] = i2;
                }
            }
            __syncthreads();
        }
        if (tid == 0) {
            topIdx[t] = sidx[0];
            g_scores[sidx[0]] = NEG_INF;    // mask; visible after next __syncthreads
        }
        __syncthreads();
    }

    // mean of selected rows (tid == column index, D_MODEL == 1024 threads)
    float s = 0.f;
#pragma unroll
    for (int t = 0; t < TOPK; t++)
        s += key_mat[(size_t)topIdx[t] * D_MODEL + tid];
    out[tid] = s * (1.0f / 6.0f);
}

// ---------------------------------------------------------------------------
extern "C" void kernel_launch(void* const* d_in, const int* in_sizes, int n_in,
                              void* d_out, int out_size) {
    const float* query   = (const float*)d_in[0];
    const float* key_mat = (const float*)d_in[1];
    const float* Wq      = (const float*)d_in[2];
    const float* bq      = (const float*)d_in[3];
    const float* Wk      = (const float*)d_in[4];
    const float* bk      = (const float*)d_in[5];
    float* out = (float*)d_out;

    k_proj_q<<<HID / 8, 256>>>(Wq, query, bq);
    dim3 gv(D_MODEL / 256, N_HCH);
    k_vpartial<<<gv, 256>>>(Wk);
    k_vreduce<<<5, 256>>>(bk);
    k_scores<<<N_KEYS / 8, 256>>>(key_mat);
    k_topk_mean<<<1, 1024>>>(key_mat, out);
}

// round 3
// speedup vs baseline: 1.0832x; 1.0832x over previous
#include <cuda_runtime.h>

#define D_MODEL 1024
#define HID     4096
#define N_KEYS  65536
#define TOPK    6
#define H_CHUNK 128
#define N_HCH   (HID / H_CHUNK)   // 32

#define PART_BLOCKS 64
#define SLICE       (N_KEYS / PART_BLOCKS)      // 1024
#define N_CAND      (PART_BLOCKS * TOPK)        // 384

// ---- scratch (no allocation allowed) ----
__device__ float g_q[HID];
__device__ float g_vpart[N_HCH * D_MODEL];
__device__ float g_v[D_MODEL];
__device__ float g_c;
__device__ float g_scores[N_KEYS];
__device__ float g_cand_val[N_CAND];
__device__ int   g_cand_idx[N_CAND];

__device__ __forceinline__ float neg_inf() { return __int_as_float(0xff800000); }

// ---------------------------------------------------------------------------
// q[h] = Wq[h,:] . query + bq[h]     (one warp per output row)
// ---------------------------------------------------------------------------
__global__ void __launch_bounds__(256) k_proj_q(const float* __restrict__ Wq,
                                                const float* __restrict__ query,
                                                const float* __restrict__ bq) {
    __shared__ float sq[D_MODEL];
    int tid = threadIdx.x;
    for (int i = tid; i < D_MODEL; i += 256) sq[i] = query[i];
    __syncthreads();

    int warp = tid >> 5, lane = tid & 31;
    int row  = blockIdx.x * 8 + warp;

    const float4* W = reinterpret_cast<const float4*>(Wq + (size_t)row * D_MODEL);
    const float4* Q = reinterpret_cast<const float4*>(sq);
    float acc = 0.f;
#pragma unroll
    for (int j = 0; j < 8; j++) {
        float4 w = __ldcs(&W[lane + 32 * j]);
        float4 q = Q[lane + 32 * j];
        acc += w.x * q.x + w.y * q.y + w.z * q.z + w.w * q.w;
    }
#pragma unroll
    for (int off = 16; off; off >>= 1)
        acc += __shfl_down_sync(0xffffffffu, acc, off);
    if (lane == 0) g_q[row] = acc + bq[row];
}

// ---------------------------------------------------------------------------
// v_partial[g, d] = sum_{h in chunk g} Wk[h,d] * q[h]
// ---------------------------------------------------------------------------
__global__ void __launch_bounds__(256) k_vpartial(const float* __restrict__ Wk) {
    __shared__ float sq[H_CHUNK];
    int tid = threadIdx.x;
    int h0  = blockIdx.y * H_CHUNK;
    if (tid < H_CHUNK) sq[tid] = g_q[h0 + tid];
    __syncthreads();

    int d = blockIdx.x * 256 + tid;
    float acc = 0.f;
#pragma unroll 4
    for (int h = 0; h < H_CHUNK; h++)
        acc += __ldcs(&Wk[(size_t)(h0 + h) * D_MODEL + d]) * sq[h];
    g_vpart[blockIdx.y * D_MODEL + d] = acc;
}

// ---------------------------------------------------------------------------
// reduce partials -> v ; block 4 computes c = bk . q
// ---------------------------------------------------------------------------
__global__ void k_vreduce(const float* __restrict__ bk) {
    if (blockIdx.x < 4) {
        int d = blockIdx.x * 256 + threadIdx.x;
        float s = 0.f;
#pragma unroll
        for (int g = 0; g < N_HCH; g++) s += g_vpart[g * D_MODEL + d];
        g_v[d] = s;
    } else {
        __shared__ float red[256];
        float s = 0.f;
        for (int h = threadIdx.x; h < HID; h += 256) s += bk[h] * g_q[h];
        red[threadIdx.x] = s;
        __syncthreads();
        for (int o = 128; o; o >>= 1) {
            if (threadIdx.x < o) red[threadIdx.x] += red[threadIdx.x + o];
            __syncthreads();
        }
        if (threadIdx.x == 0) g_c = red[0];
    }
}

// ---------------------------------------------------------------------------
// scores[n] = key_mat[n,:] . v + c   (one warp per row; 256 MB streamed)
// ---------------------------------------------------------------------------
__global__ void __launch_bounds__(256) k_scores(const float* __restrict__ key_mat) {
    __shared__ float sv[D_MODEL];
    int tid = threadIdx.x;
    for (int i = tid; i < D_MODEL; i += 256) sv[i] = g_v[i];
    __syncthreads();

    int warp = tid >> 5, lane = tid & 31;
    int row  = blockIdx.x * 8 + warp;

    const float4* K = reinterpret_cast<const float4*>(key_mat + (size_t)row * D_MODEL);
    const float4* V = reinterpret_cast<const float4*>(sv);
    float acc = 0.f;
#pragma unroll
    for (int j = 0; j < 8; j++) {
        float4 k = __ldcs(&K[lane + 32 * j]);
        float4 v = V[lane + 32 * j];
        acc += k.x * v.x + k.y * v.y + k.z * v.z + k.w * v.w;
    }
#pragma unroll
    for (int off = 16; off; off >>= 1)
        acc += __shfl_down_sync(0xffffffffu, acc, off);
    if (lane == 0) g_scores[row] = acc + g_c;
}

// ---------------------------------------------------------------------------
// Stage A: per-block top-6 of a 1024-score slice (6 masked argmax passes in
// smem; lowest index wins ties, matching jnp.argmax / the torch loop).
// ---------------------------------------------------------------------------
__global__ void __launch_bounds__(256) k_topk_partial() {
    __shared__ float ss[SLICE];
    __shared__ float rval[256];
    __shared__ int   ridx[256];
    int tid  = threadIdx.x;
    int base = blockIdx.x * SLICE;

    for (int i = tid; i < SLICE; i += 256) ss[i] = g_scores[base + i];
    __syncthreads();

    for (int t = 0; t < TOPK; t++) {
        float best = neg_inf();
        int   bidx = SLICE;
        for (int i = tid; i < SLICE; i += 256) {
            float s = ss[i];
            if (s > best) { best = s; bidx = i; }   // '>' keeps lowest index per thread
        }
        rval[tid] = best; ridx[tid] = bidx;
        __syncthreads();
        for (int o = 128; o; o >>= 1) {
            if (tid < o) {
                float v2 = rval[tid + o]; int i2 = ridx[tid + o];
                if (v2 > rval[tid] || (v2 == rval[tid] && i2 < ridx[tid])) {
                    rval[tid] = v2; ridx[tid] = i2;
                }
            }
            __syncthreads();
        }
        if (tid == 0) {
            g_cand_val[blockIdx.x * TOPK + t] = rval[0];
            g_cand_idx[blockIdx.x * TOPK + t] = base + ridx[0];
            ss[ridx[0]] = neg_inf();
        }
        __syncthreads();
    }
}

// ---------------------------------------------------------------------------
// Stage B: merge 384 candidates (6 sequential argmax, value-then-lower-index),
// then out = mean of the 6 selected key rows.
// ---------------------------------------------------------------------------
__global__ void __launch_bounds__(1024) k_topk_final(const float* __restrict__ key_mat,
                                                     float* __restrict__ out) {
    __shared__ float cv[N_CAND];
    __shared__ int   ci[N_CAND];
    __shared__ float rval[1024];
    __shared__ int   rslot[1024];
    __shared__ int   topIdx[TOPK];
    int tid = threadIdx.x;

    if (tid < N_CAND) { cv[tid] = g_cand_val[tid]; ci[tid] = g_cand_idx[tid]; }
    __syncthreads();

    for (int t = 0; t < TOPK; t++) {
        float v = (tid < N_CAND) ? cv[tid] : neg_inf();
        rval[tid] = v; rslot[tid] = tid;
        __syncthreads();
        for (int o = 512; o; o >>= 1) {
            if (tid < o) {
                float v2 = rval[tid + o]; int s2 = rslot[tid + o];
                int   s1 = rslot[tid];
                bool take = (v2 > rval[tid]) ||
                            (v2 == rval[tid] && s2 < N_CAND && s1 < N_CAND &&
                             ci[s2] < ci[s1]);
                if (take) { rval[tid] = v2; rslot[tid] = s2; }
            }
            __syncthreads();
        }
        if (tid == 0) {
            int slot = rslot[0];
            topIdx[t] = ci[slot];
            cv[slot]  = neg_inf();
        }
        __syncthreads();
    }

    // mean of selected rows (tid == column index)
    float s = 0.f;
#pragma unroll
    for (int t = 0; t < TOPK; t++)
        s += key_mat[(size_t)topIdx[t] * D_MODEL + tid];
    out[tid] = s * (1.0f / 6.0f);
}

// ---------------------------------------------------------------------------
extern "C" void kernel_launch(void* const* d_in, const int* in_sizes, int n_in,
                              void* d_out, int out_size) {
    const float* query   = (const float*)d_in[0];
    const float* key_mat = (const float*)d_in[1];
    const float* Wq      = (const float*)d_in[2];
    const float* bq      = (const float*)d_in[3];
    const float* Wk      = (const float*)d_in[4];
    const float* bk      = (const float*)d_in[5];
    float* out = (float*)d_out;

    k_proj_q<<<HID / 8, 256>>>(Wq, query, bq);
    dim3 gv(D_MODEL / 256, N_HCH);
    k_vpartial<<<gv, 256>>>(Wk);
    k_vreduce<<<5, 256>>>(bk);
    k_scores<<<N_KEYS / 8, 256>>>(key_mat);
    k_topk_partial<<<PART_BLOCKS, 256>>>();
    k_topk_final<<<1, 1024>>>(key_mat, out);
}

// round 4
// speedup vs baseline: 1.0889x; 1.0053x over previous
#include <cuda_runtime.h>

#define D_MODEL 1024
#define HID     4096
#define N_KEYS  65536
#define TOPK    6

#define H_CHUNK 32
#define N_HCH   (HID / H_CHUNK)          // 128 blocks for k_qv

#define ROWS_PER_BLK 64
#define SC_BLOCKS    (N_KEYS / ROWS_PER_BLK)   // 1024
#define N_CAND       (SC_BLOCKS * TOPK)        // 6144

// ---- scratch (no allocation allowed) ----
__device__ float g_q[HID];
__device__ float g_vpart[N_HCH * D_MODEL];
__device__ float g_v[D_MODEL];
__device__ float g_c;
__device__ float g_cand_val[N_CAND];
__device__ int   g_cand_idx[N_CAND];

__device__ __forceinline__ float neg_inf() { return __int_as_float(0xff800000); }

// ---------------------------------------------------------------------------
// Fused: q[h] = Wq[h,:].query + bq[h] for this block's 32-row h-chunk, then
// vpart[chunk,d] = sum_{h in chunk} Wk[h,d] * q[h].  128 blocks x 256 thr.
// ---------------------------------------------------------------------------
__global__ void __launch_bounds__(256) k_qv(const float* __restrict__ Wq,
                                            const float* __restrict__ query,
                                            const float* __restrict__ bq,
                                            const float* __restrict__ Wk) {
    __shared__ float sq[D_MODEL];     // query vector
    __shared__ float sqr[H_CHUNK];    // this chunk's q values
    int tid  = threadIdx.x;
    int h0   = blockIdx.x * H_CHUNK;

    for (int i = tid; i < D_MODEL; i += 256) sq[i] = query[i];
    __syncthreads();

    // Phase A: 8 warps x 4 rows each
    int warp = tid >> 5, lane = tid & 31;
    const float4* Q = reinterpret_cast<const float4*>(sq);
#pragma unroll
    for (int r = 0; r < 4; r++) {
        int h = h0 + warp * 4 + r;
        const float4* W = reinterpret_cast<const float4*>(Wq + (size_t)h * D_MODEL);
        float acc = 0.f;
#pragma unroll
        for (int j = 0; j < 8; j++) {
            float4 w = __ldcs(&W[lane + 32 * j]);
            float4 q = Q[lane + 32 * j];
            acc += w.x * q.x + w.y * q.y + w.z * q.z + w.w * q.w;
        }
#pragma unroll
        for (int off = 16; off; off >>= 1)
            acc += __shfl_down_sync(0xffffffffu, acc, off);
        if (lane == 0) {
            float qv = acc + bq[h];
            sqr[warp * 4 + r] = qv;
            g_q[h] = qv;                       // needed for c = bk.q
        }
    }
    __syncthreads();

    // Phase B: each thread owns 4 d's (d = tid + 256*j), coalesced Wk reads
    float acc0 = 0.f, acc1 = 0.f, acc2 = 0.f, acc3 = 0.f;
#pragma unroll 4
    for (int h = 0; h < H_CHUNK; h++) {
        const float* row = Wk + (size_t)(h0 + h) * D_MODEL;
        float qh = sqr[h];
        acc0 += __ldcs(&row[tid      ]) * qh;
        acc1 += __ldcs(&row[tid + 256]) * qh;
        acc2 += __ldcs(&row[tid + 512]) * qh;
        acc3 += __ldcs(&row[tid + 768]) * qh;
    }
    float* vp = g_vpart + (size_t)blockIdx.x * D_MODEL;
    vp[tid      ] = acc0;
    vp[tid + 256] = acc1;
    vp[tid + 512] = acc2;
    vp[tid + 768] = acc3;
}

// ---------------------------------------------------------------------------
// reduce partials -> v ; block 4 computes c = bk . q
// ---------------------------------------------------------------------------
__global__ void __launch_bounds__(256) k_vreduce(const float* __restrict__ bk) {
    if (blockIdx.x < 4) {
        int d = blockIdx.x * 256 + threadIdx.x;
        float s = 0.f;
#pragma unroll 8
        for (int g = 0; g < N_HCH; g++) s += g_vpart[(size_t)g * D_MODEL + d];
        g_v[d] = s;
    } else {
        __shared__ float red[256];
        float s = 0.f;
        for (int h = threadIdx.x; h < HID; h += 256) s += bk[h] * g_q[h];
        red[threadIdx.x] = s;
        __syncthreads();
        for (int o = 128; o; o >>= 1) {
            if (threadIdx.x < o) red[threadIdx.x] += red[threadIdx.x + o];
            __syncthreads();
        }
        if (threadIdx.x == 0) g_c = red[0];
    }
}

// ---------------------------------------------------------------------------
// Fused scores + per-block top-6.  1024 blocks x 256 threads, 64 rows/block.
// scores[n] = key_mat[n,:].v + c ; local top-6 (lowest index wins ties).
// ---------------------------------------------------------------------------
__global__ void __launch_bounds__(256) k_scores_topk(const float* __restrict__ key_mat) {
    __shared__ float sv[D_MODEL];
    __shared__ float ss[ROWS_PER_BLK];
    __shared__ float rv[64];
    __shared__ int   ri[64];
    int tid = threadIdx.x;

    for (int i = tid; i < D_MODEL; i += 256) sv[i] = g_v[i];
    __syncthreads();

    int warp = tid >> 5, lane = tid & 31;
    int rowBase = blockIdx.x * ROWS_PER_BLK;
    const float4* V = reinterpret_cast<const float4*>(sv);
    float c = g_c;

#pragma unroll
    for (int it = 0; it < 8; it++) {                 // 8 iterations x 8 warps
        int r   = it * 8 + warp;
        const float4* K = reinterpret_cast<const float4*>(
            key_mat + (size_t)(rowBase + r) * D_MODEL);
        float acc = 0.f;
#pragma unroll
        for (int j = 0; j < 8; j++) {
            float4 k = __ldcs(&K[lane + 32 * j]);
            float4 v = V[lane + 32 * j];
            acc += k.x * v.x + k.y * v.y + k.z * v.z + k.w * v.w;
        }
#pragma unroll
        for (int off = 16; off; off >>= 1)
            acc += __shfl_down_sync(0xffffffffu, acc, off);
        if (lane == 0) ss[r] = acc + c;
    }
    __syncthreads();

    // local top-6 over 64 scores using first 64 threads
    for (int t = 0; t < TOPK; t++) {
        if (tid < 64) { rv[tid] = ss[tid]; ri[tid] = tid; }
        __syncthreads();
#pragma unroll
        for (int o = 32; o; o >>= 1) {
            if (tid < o) {
                float v2 = rv[tid + o]; int i2 = ri[tid + o];
                if (v2 > rv[tid] || (v2 == rv[tid] && i2 < ri[tid])) {
                    rv[tid] = v2; ri[tid] = i2;
                }
            }
            __syncthreads();
        }
        if (tid == 0) {
            g_cand_val[blockIdx.x * TOPK + t] = rv[0];
            g_cand_idx[blockIdx.x * TOPK + t] = rowBase + ri[0];
            ss[ri[0]] = neg_inf();
        }
        __syncthreads();
    }
}

// ---------------------------------------------------------------------------
// Merge 6144 candidates (6 sequential argmax, value then lower global index),
// then out = mean of the 6 selected key rows.
// ---------------------------------------------------------------------------
__global__ void __launch_bounds__(1024) k_topk_final(const float* __restrict__ key_mat,
                                                     float* __restrict__ out) {
    __shared__ float cv[N_CAND];
    __shared__ int   ci[N_CAND];
    __shared__ float rval[1024];
    __shared__ int   rslot[1024];
    __shared__ int   topIdx[TOPK];
    int tid = threadIdx.x;

#pragma unroll
    for (int j = 0; j < N_CAND / 1024; j++) {
        cv[tid + 1024 * j] = g_cand_val[tid + 1024 * j];
        ci[tid + 1024 * j] = g_cand_idx[tid + 1024 * j];
    }
    __syncthreads();

    for (int t = 0; t < TOPK; t++) {
        // thread-local best over 6 strided candidates (lower slot first)
        float best = neg_inf(); int bslot = -1;
#pragma unroll
        for (int j = 0; j < N_CAND / 1024; j++) {
            int s = tid + 1024 * j;
            float v = cv[s];
            if (v > best || (v == best && bslot >= 0 && ci[s] < ci[bslot])) {
                best = v; bslot = s;
            }
        }
        rval[tid] = best; rslot[tid] = bslot;
        __syncthreads();
        for (int o = 512; o; o >>= 1) {
            if (tid < o) {
                float v2 = rval[tid + o]; int s2 = rslot[tid + o];
                int   s1 = rslot[tid];
                bool take = (v2 > rval[tid]) ||
                            (v2 == rval[tid] && s2 >= 0 &&
                             (s1 < 0 || ci[s2] < ci[s1]));
                if (take) { rval[tid] = v2; rslot[tid] = s2; }
            }
            __syncthreads();
        }
        if (tid == 0) {
            int slot = rslot[0];
            topIdx[t] = ci[slot];
            cv[slot]  = neg_inf();
        }
        __syncthreads();
    }

    // mean of selected rows (tid == column index)
    float s = 0.f;
#pragma unroll
    for (int t = 0; t < TOPK; t++)
        s += key_mat[(size_t)topIdx[t] * D_MODEL + tid];
    out[tid] = s * (1.0f / 6.0f);
}

// ---------------------------------------------------------------------------
extern "C" void kernel_launch(void* const* d_in, const int* in_sizes, int n_in,
                              void* d_out, int out_size) {
    const float* query   = (const float*)d_in[0];
    const float* key_mat = (const float*)d_in[1];
    const float* Wq      = (const float*)d_in[2];
    const float* bq      = (const float*)d_in[3];
    const float* Wk      = (const float*)d_in[4];
    const float* bk      = (const float*)d_in[5];
    float* out = (float*)d_out;

    k_qv<<<N_HCH, 256>>>(Wq, query, bq, Wk);
    k_vreduce<<<5, 256>>>(bk);
    k_scores_topk<<<SC_BLOCKS, 256>>>(key_mat);
    k_topk_final<<<1, 1024>>>(key_mat, out);
}

// round 5
// speedup vs baseline: 1.2709x; 1.1671x over previous
#include <cuda_runtime.h>

#define D_MODEL 1024
#define HID     4096
#define N_KEYS  65536
#define TOPK    6

#define H_CHUNK 16
#define N_HCH   (HID / H_CHUNK)                // 256 blocks for k_qv

#define ROWS_PER_BLK 64
#define SC_BLOCKS    (N_KEYS / ROWS_PER_BLK)   // 1024
#define N_CAND       (SC_BLOCKS * TOPK)        // 6144

typedef unsigned long long u64;

// ---- scratch (no allocation allowed) ----
__device__ float g_q[HID];
__device__ float g_vpart[N_HCH * D_MODEL];
__device__ float g_v[D_MODEL];
__device__ float g_c;
__device__ u64   g_cand[N_CAND];

// sortable key: higher key <=> greater value, ties -> lower index wins
__device__ __forceinline__ u64 make_key(float v, int idx) {
    unsigned u = __float_as_uint(v);
    u = (u & 0x80000000u) ? ~u : (u | 0x80000000u);
    return ((u64)u << 32) | (unsigned)(~idx);
}
__device__ __forceinline__ int key_idx(u64 k) { return ~(unsigned)(k & 0xffffffffu); }

__device__ __forceinline__ u64 warp_max_u64(u64 k) {
#pragma unroll
    for (int o = 16; o; o >>= 1) {
        u64 other = __shfl_xor_sync(0xffffffffu, k, o);
        if (other > k) k = other;
    }
    return k;
}

// ---------------------------------------------------------------------------
// Fused: q[h] for this block's 16-row h-chunk, then its partial-v contribution.
// 256 blocks x 256 threads.
// ---------------------------------------------------------------------------
__global__ void __launch_bounds__(256) k_qv(const float* __restrict__ Wq,
                                            const float* __restrict__ query,
                                            const float* __restrict__ bq,
                                            const float* __restrict__ Wk) {
    __shared__ float sq[D_MODEL];
    __shared__ float sqr[H_CHUNK];
    int tid = threadIdx.x;
    int h0  = blockIdx.x * H_CHUNK;

    for (int i = tid; i < D_MODEL; i += 256) sq[i] = query[i];
    __syncthreads();

    // Phase A: 8 warps x 2 rows each
    int warp = tid >> 5, lane = tid & 31;
    const float4* Q = reinterpret_cast<const float4*>(sq);
#pragma unroll
    for (int r = 0; r < 2; r++) {
        int h = h0 + warp * 2 + r;
        const float4* W = reinterpret_cast<const float4*>(Wq + (size_t)h * D_MODEL);
        float acc = 0.f;
#pragma unroll
        for (int j = 0; j < 8; j++) {
            float4 w = __ldcs(&W[lane + 32 * j]);
            float4 q = Q[lane + 32 * j];
            acc += w.x * q.x + w.y * q.y + w.z * q.z + w.w * q.w;
        }
#pragma unroll
        for (int off = 16; off; off >>= 1)
            acc += __shfl_down_sync(0xffffffffu, acc, off);
        if (lane == 0) {
            float qv = acc + bq[h];
            sqr[warp * 2 + r] = qv;
            g_q[h] = qv;
        }
    }
    __syncthreads();

    // Phase B: each thread owns 4 d's, coalesced Wk reads
    float acc0 = 0.f, acc1 = 0.f, acc2 = 0.f, acc3 = 0.f;
#pragma unroll
    for (int h = 0; h < H_CHUNK; h++) {
        const float* row = Wk + (size_t)(h0 + h) * D_MODEL;
        float qh = sqr[h];
        acc0 += __ldcs(&row[tid      ]) * qh;
        acc1 += __ldcs(&row[tid + 256]) * qh;
        acc2 += __ldcs(&row[tid + 512]) * qh;
        acc3 += __ldcs(&row[tid + 768]) * qh;
    }
    float* vp = g_vpart + (size_t)blockIdx.x * D_MODEL;
    vp[tid      ] = acc0;
    vp[tid + 256] = acc1;
    vp[tid + 512] = acc2;
    vp[tid + 768] = acc3;
}

// ---------------------------------------------------------------------------
// reduce partials -> v ; block 4 computes c = bk . q
// ---------------------------------------------------------------------------
__global__ void __launch_bounds__(256) k_vreduce(const float* __restrict__ bk) {
    if (blockIdx.x < 4) {
        int d = blockIdx.x * 256 + threadIdx.x;
        float s = 0.f;
#pragma unroll 8
        for (int g = 0; g < N_HCH; g++) s += g_vpart[(size_t)g * D_MODEL + d];
        g_v[d] = s;
    } else {
        __shared__ float red[256];
        float s = 0.f;
        for (int h = threadIdx.x; h < HID; h += 256) s += bk[h] * g_q[h];
        red[threadIdx.x] = s;
        __syncthreads();
        for (int o = 128; o; o >>= 1) {
            if (threadIdx.x < o) red[threadIdx.x] += red[threadIdx.x + o];
            __syncthreads();
        }
        if (threadIdx.x == 0) g_c = red[0];
    }
}

// ---------------------------------------------------------------------------
// Fused scores + per-block top-6 (u64 keys, warp-0 only, no block syncs in
// the pick loop). 1024 blocks x 256 threads, 64 rows/block.
// ---------------------------------------------------------------------------
__global__ void __launch_bounds__(256) k_scores_topk(const float* __restrict__ key_mat) {
    __shared__ float sv[D_MODEL];
    __shared__ float ss[ROWS_PER_BLK];
    int tid = threadIdx.x;

    for (int i = tid; i < D_MODEL; i += 256) sv[i] = g_v[i];
    __syncthreads();

    int warp = tid >> 5, lane = tid & 31;
    int rowBase = blockIdx.x * ROWS_PER_BLK;
    const float4* V = reinterpret_cast<const float4*>(sv);
    float c = g_c;

#pragma unroll
    for (int it = 0; it < 8; it++) {
        int r = it * 8 + warp;
        const float4* K = reinterpret_cast<const float4*>(
            key_mat + (size_t)(rowBase + r) * D_MODEL);
        float acc = 0.f;
#pragma unroll
        for (int j = 0; j < 8; j++) {
            float4 k = __ldcs(&K[lane + 32 * j]);
            float4 v = V[lane + 32 * j];
            acc += k.x * v.x + k.y * v.y + k.z * v.z + k.w * v.w;
        }
#pragma unroll
        for (int off = 16; off; off >>= 1)
            acc += __shfl_down_sync(0xffffffffu, acc, off);
        if (lane == 0) ss[r] = acc + c;
    }
    __syncthreads();

    // warp 0 selects top-6 of the 64 scores; keys in registers, shfl only
    if (warp == 0) {
        u64 k0 = make_key(ss[lane],      rowBase + lane);
        u64 k1 = make_key(ss[lane + 32], rowBase + lane + 32);
#pragma unroll
        for (int t = 0; t < TOPK; t++) {
            u64 mine = (k0 > k1) ? k0 : k1;
            u64 win  = warp_max_u64(mine);
            if (lane == t % 32)  // any single lane works; spread writes
                ;
            if (lane == 0) g_cand[blockIdx.x * TOPK + t] = win;
            if (k0 == win) k0 = 0;
            if (k1 == win) k1 = 0;
        }
    }
}

// ---------------------------------------------------------------------------
// Merge 6144 u64 candidates: 6 passes, each = local max -> warp shfl max ->
// 32-way warp-0 max (2 barriers per pass). Then mean of the 6 key rows.
// ---------------------------------------------------------------------------
__global__ void __launch_bounds__(1024) k_topk_final(const float* __restrict__ key_mat,
                                                     float* __restrict__ out) {
    __shared__ u64 swarp[32];
    __shared__ u64 swin;
    int tid = threadIdx.x;
    int warp = tid >> 5, lane = tid & 31;

    // 6 keys per thread, register-resident
    u64 k[6];
#pragma unroll
    for (int j = 0; j < 6; j++) k[j] = g_cand[tid + 1024 * j];

    int topIdx[TOPK];

#pragma unroll
    for (int t = 0; t < TOPK; t++) {
        u64 best = k[0];
#pragma unroll
        for (int j = 1; j < 6; j++) if (k[j] > best) best = k[j];
        best = warp_max_u64(best);
        if (lane == 0) swarp[warp] = best;
        __syncthreads();
        if (warp == 0) {
            u64 b = swarp[lane];
            b = warp_max_u64(b);
            if (lane == 0) swin = b;
        }
        __syncthreads();
        u64 win = swin;
        topIdx[t] = key_idx(win);
#pragma unroll
        for (int j = 0; j < 6; j++) if (k[j] == win) k[j] = 0;
        __syncthreads();
    }

    // mean of selected rows (tid == column index)
    float s = 0.f;
#pragma unroll
    for (int t = 0; t < TOPK; t++)
        s += key_mat[(size_t)topIdx[t] * D_MODEL + tid];
    out[tid] = s * (1.0f / 6.0f);
}

// ---------------------------------------------------------------------------
extern "C" void kernel_launch(void* const* d_in, const int* in_sizes, int n_in,
                              void* d_out, int out_size) {
    const float* query   = (const float*)d_in[0];
    const float* key_mat = (const float*)d_in[1];
    const float* Wq      = (const float*)d_in[2];
    const float* bq      = (const float*)d_in[3];
    const float* Wk      = (const float*)d_in[4];
    const float* bk      = (const float*)d_in[5];
    float* out = (float*)d_out;

    k_qv<<<N_HCH, 256>>>(Wq, query, bq, Wk);
    k_vreduce<<<5, 256>>>(bk);
    k_scores_topk<<<SC_BLOCKS, 256>>>(key_mat);
    k_topk_final<<<1, 1024>>>(key_mat, out);
}

// round 6
// speedup vs baseline: 1.2751x; 1.0033x over previous
#include <cuda_runtime.h>

#define D_MODEL 1024
#define HID     4096
#define N_KEYS  65536
#define TOPK    6

#define H_CHUNK 16
#define N_HCH   (HID / H_CHUNK)                // 256 blocks for k_qv

#define ROWS_PER_BLK 64
#define SC_BLOCKS    (N_KEYS / ROWS_PER_BLK)   // 1024
#define N_CAND       (SC_BLOCKS * TOPK)        // 6144

typedef unsigned long long u64;

// ---- scratch (no allocation allowed) ----
__device__ float g_q[HID];
__device__ float g_vpart[N_HCH * D_MODEL];
__device__ float g_v[D_MODEL];
__device__ float g_c;
__device__ u64   g_cand[N_CAND];

// sortable key: higher key <=> greater value, ties -> lower index wins
__device__ __forceinline__ u64 make_key(float v, int idx) {
    unsigned u = __float_as_uint(v);
    u = (u & 0x80000000u) ? ~u : (u | 0x80000000u);
    return ((u64)u << 32) | (unsigned)(~idx);
}
__device__ __forceinline__ int key_idx(u64 k) { return ~(unsigned)(k & 0xffffffffu); }

__device__ __forceinline__ u64 warp_max_u64(u64 k) {
#pragma unroll
    for (int o = 16; o; o >>= 1) {
        u64 other = __shfl_xor_sync(0xffffffffu, k, o);
        if (other > k) k = other;
    }
    return k;
}

// ---------------------------------------------------------------------------
// Fused: q[h] for this block's 16-row h-chunk, then its partial-v contribution.
// 256 blocks x 256 threads.
// ---------------------------------------------------------------------------
__global__ void __launch_bounds__(256) k_qv(const float* __restrict__ Wq,
                                            const float* __restrict__ query,
                                            const float* __restrict__ bq,
                                            const float* __restrict__ Wk) {
    __shared__ float sq[D_MODEL];
    __shared__ float sqr[H_CHUNK];
    int tid = threadIdx.x;
    int h0  = blockIdx.x * H_CHUNK;

    for (int i = tid; i < D_MODEL; i += 256) sq[i] = query[i];
    __syncthreads();

    // Phase A: 8 warps x 2 rows each
    int warp = tid >> 5, lane = tid & 31;
    const float4* Q = reinterpret_cast<const float4*>(sq);
#pragma unroll
    for (int r = 0; r < 2; r++) {
        int h = h0 + warp * 2 + r;
        const float4* W = reinterpret_cast<const float4*>(Wq + (size_t)h * D_MODEL);
        float acc = 0.f;
#pragma unroll
        for (int j = 0; j < 8; j++) {
            float4 w = __ldcs(&W[lane + 32 * j]);
            float4 q = Q[lane + 32 * j];
            acc += w.x * q.x + w.y * q.y + w.z * q.z + w.w * q.w;
        }
#pragma unroll
        for (int off = 16; off; off >>= 1)
            acc += __shfl_down_sync(0xffffffffu, acc, off);
        if (lane == 0) {
            float qv = acc + bq[h];
            sqr[warp * 2 + r] = qv;
            g_q[h] = qv;
        }
    }
    __syncthreads();

    // Phase B: each thread owns 4 d's, coalesced Wk reads
    float acc0 = 0.f, acc1 = 0.f, acc2 = 0.f, acc3 = 0.f;
#pragma unroll
    for (int h = 0; h < H_CHUNK; h++) {
        const float* row = Wk + (size_t)(h0 + h) * D_MODEL;
        float qh = sqr[h];
        acc0 += __ldcs(&row[tid      ]) * qh;
        acc1 += __ldcs(&row[tid + 256]) * qh;
        acc2 += __ldcs(&row[tid + 512]) * qh;
        acc3 += __ldcs(&row[tid + 768]) * qh;
    }
    float* vp = g_vpart + (size_t)blockIdx.x * D_MODEL;
    vp[tid      ] = acc0;
    vp[tid + 256] = acc1;
    vp[tid + 512] = acc2;
    vp[tid + 768] = acc3;
}

// ---------------------------------------------------------------------------
// reduce partials -> v ; block 4 computes c = bk . q
// ---------------------------------------------------------------------------
__global__ void __launch_bounds__(256) k_vreduce(const float* __restrict__ bk) {
    if (blockIdx.x < 4) {
        int d = blockIdx.x * 256 + threadIdx.x;
        float s = 0.f;
#pragma unroll 8
        for (int g = 0; g < N_HCH; g++) s += g_vpart[(size_t)g * D_MODEL + d];
        g_v[d] = s;
    } else {
        __shared__ float red[256];
        float s = 0.f;
        for (int h = threadIdx.x; h < HID; h += 256) s += bk[h] * g_q[h];
        red[threadIdx.x] = s;
        __syncthreads();
        for (int o = 128; o; o >>= 1) {
            if (threadIdx.x < o) red[threadIdx.x] += red[threadIdx.x + o];
            __syncthreads();
        }
        if (threadIdx.x == 0) g_c = red[0];
    }
}

// ---------------------------------------------------------------------------
// Fused scores + per-block top-6 (u64 keys, warp-0 only, no block syncs in
// the pick loop). 1024 blocks x 256 threads, 64 rows/block.
// ---------------------------------------------------------------------------
__global__ void __launch_bounds__(256) k_scores_topk(const float* __restrict__ key_mat) {
    __shared__ float sv[D_MODEL];
    __shared__ float ss[ROWS_PER_BLK];
    int tid = threadIdx.x;

    for (int i = tid; i < D_MODEL; i += 256) sv[i] = g_v[i];
    __syncthreads();

    int warp = tid >> 5, lane = tid & 31;
    int rowBase = blockIdx.x * ROWS_PER_BLK;
    const float4* V = reinterpret_cast<const float4*>(sv);
    float c = g_c;

#pragma unroll
    for (int it = 0; it < 8; it++) {
        int r = it * 8 + warp;
        const float4* K = reinterpret_cast<const float4*>(
            key_mat + (size_t)(rowBase + r) * D_MODEL);
        float acc = 0.f;
#pragma unroll
        for (int j = 0; j < 8; j++) {
            float4 k = __ldcs(&K[lane + 32 * j]);
            float4 v = V[lane + 32 * j];
            acc += k.x * v.x + k.y * v.y + k.z * v.z + k.w * v.w;
        }
#pragma unroll
        for (int off = 16; off; off >>= 1)
            acc += __shfl_down_sync(0xffffffffu, acc, off);
        if (lane == 0) ss[r] = acc + c;
    }
    __syncthreads();

    // warp 0 selects top-6 of the 64 scores; keys in registers, shfl only
    if (warp == 0) {
        u64 k0 = make_key(ss[lane],      rowBase + lane);
        u64 k1 = make_key(ss[lane + 32], rowBase + lane + 32);
#pragma unroll
        for (int t = 0; t < TOPK; t++) {
            u64 mine = (k0 > k1) ? k0 : k1;
            u64 win  = warp_max_u64(mine);
            if (lane == t % 32)  // any single lane works; spread writes
                ;
            if (lane == 0) g_cand[blockIdx.x * TOPK + t] = win;
            if (k0 == win) k0 = 0;
            if (k1 == win) k1 = 0;
        }
    }
}

// ---------------------------------------------------------------------------
// Merge 6144 u64 candidates: 6 passes, each = local max -> warp shfl max ->
// 32-way warp-0 max (2 barriers per pass). Then mean of the 6 key rows.
// ---------------------------------------------------------------------------
__global__ void __launch_bounds__(1024) k_topk_final(const float* __restrict__ key_mat,
                                                     float* __restrict__ out) {
    __shared__ u64 swarp[32];
    __shared__ u64 swin;
    int tid = threadIdx.x;
    int warp = tid >> 5, lane = tid & 31;

    // 6 keys per thread, register-resident
    u64 k[6];
#pragma unroll
    for (int j = 0; j < 6; j++) k[j] = g_cand[tid + 1024 * j];

    int topIdx[TOPK];

#pragma unroll
    for (int t = 0; t < TOPK; t++) {
        u64 best = k[0];
#pragma unroll
        for (int j = 1; j < 6; j++) if (k[j] > best) best = k[j];
        best = warp_max_u64(best);
        if (lane == 0) swarp[warp] = best;
        __syncthreads();
        if (warp == 0) {
            u64 b = swarp[lane];
            b = warp_max_u64(b);
            if (lane == 0) swin = b;
        }
        __syncthreads();
        u64 win = swin;
        topIdx[t] = key_idx(win);
#pragma unroll
        for (int j = 0; j < 6; j++) if (k[j] == win) k[j] = 0;
        __syncthreads();
    }

    // mean of selected rows (tid == column index)
    float s = 0.f;
#pragma unroll
    for (int t = 0; t < TOPK; t++)
        s += key_mat[(size_t)topIdx[t] * D_MODEL + tid];
    out[tid] = s * (1.0f / 6.0f);
}

// ---------------------------------------------------------------------------
extern "C" void kernel_launch(void* const* d_in, const int* in_sizes, int n_in,
                              void* d_out, int out_size) {
    const float* query   = (const float*)d_in[0];
    const float* key_mat = (const float*)d_in[1];
    const float* Wq      = (const float*)d_in[2];
    const float* bq      = (const float*)d_in[3];
    const float* Wk      = (const float*)d_in[4];
    const float* bk      = (const float*)d_in[5];
    float* out = (float*)d_out;

    k_qv<<<N_HCH, 256>>>(Wq, query, bq, Wk);
    k_vreduce<<<5, 256>>>(bk);
    k_scores_topk<<<SC_BLOCKS, 256>>>(key_mat);
    k_topk_final<<<1, 1024>>>(key_mat, out);
}

// round 7
// speedup vs baseline: 1.3114x; 1.0285x over previous
#include <cuda_runtime.h>

#define D_MODEL 1024
#define HID     4096
#define N_KEYS  65536
#define TOPK    6

#define H_CHUNK 16
#define N_HCH   (HID / H_CHUNK)                // 256 blocks for k_qv

#define ROWS_PER_BLK 64
#define SC_BLOCKS    (N_KEYS / ROWS_PER_BLK)   // 1024
#define N_CAND       (SC_BLOCKS * TOPK)        // 6144
#define CAND_PER_THR (N_CAND / 256)            // 24

typedef unsigned long long u64;

// ---- scratch (no allocation allowed) ----
__device__ float g_q[HID];
__device__ float g_vpart[N_HCH * D_MODEL];
__device__ float g_v[D_MODEL];
__device__ float g_c;
__device__ u64   g_cand[N_CAND];
__device__ int   g_ctr;                        // zero-init; reset by last block

// sortable key: higher key <=> greater value, ties -> lower index wins
__device__ __forceinline__ u64 make_key(float v, int idx) {
    unsigned u = __float_as_uint(v);
    u = (u & 0x80000000u) ? ~u : (u | 0x80000000u);
    return ((u64)u << 32) | (unsigned)(~idx);
}
__device__ __forceinline__ int key_idx(u64 k) { return ~(unsigned)(k & 0xffffffffu); }

__device__ __forceinline__ u64 warp_max_u64(u64 k) {
#pragma unroll
    for (int o = 16; o; o >>= 1) {
        u64 other = __shfl_xor_sync(0xffffffffu, k, o);
        if (other > k) k = other;
    }
    return k;
}

// ---------------------------------------------------------------------------
// Fused: q[h] for this block's 16-row h-chunk, then its partial-v contribution.
// ---------------------------------------------------------------------------
__global__ void __launch_bounds__(256) k_qv(const float* __restrict__ Wq,
                                            const float* __restrict__ query,
                                            const float* __restrict__ bq,
                                            const float* __restrict__ Wk) {
    __shared__ float sq[D_MODEL];
    __shared__ float sqr[H_CHUNK];
    int tid = threadIdx.x;
    int h0  = blockIdx.x * H_CHUNK;

    for (int i = tid; i < D_MODEL; i += 256) sq[i] = query[i];
    __syncthreads();

    int warp = tid >> 5, lane = tid & 31;
    const float4* Q = reinterpret_cast<const float4*>(sq);
#pragma unroll
    for (int r = 0; r < 2; r++) {
        int h = h0 + warp * 2 + r;
        const float4* W = reinterpret_cast<const float4*>(Wq + (size_t)h * D_MODEL);
        float acc = 0.f;
#pragma unroll
        for (int j = 0; j < 8; j++) {
            float4 w = __ldcs(&W[lane + 32 * j]);
            float4 q = Q[lane + 32 * j];
            acc += w.x * q.x + w.y * q.y + w.z * q.z + w.w * q.w;
        }
#pragma unroll
        for (int off = 16; off; off >>= 1)
            acc += __shfl_down_sync(0xffffffffu, acc, off);
        if (lane == 0) {
            float qv = acc + bq[h];
            sqr[warp * 2 + r] = qv;
            g_q[h] = qv;
        }
    }
    __syncthreads();

    float acc0 = 0.f, acc1 = 0.f, acc2 = 0.f, acc3 = 0.f;
#pragma unroll
    for (int h = 0; h < H_CHUNK; h++) {
        const float* row = Wk + (size_t)(h0 + h) * D_MODEL;
        float qh = sqr[h];
        acc0 += __ldcs(&row[tid      ]) * qh;
        acc1 += __ldcs(&row[tid + 256]) * qh;
        acc2 += __ldcs(&row[tid + 512]) * qh;
        acc3 += __ldcs(&row[tid + 768]) * qh;
    }
    float* vp = g_vpart + (size_t)blockIdx.x * D_MODEL;
    vp[tid      ] = acc0;
    vp[tid + 256] = acc1;
    vp[tid + 512] = acc2;
    vp[tid + 768] = acc3;
}

// ---------------------------------------------------------------------------
// reduce partials -> v ; block 4 computes c = bk . q
// ---------------------------------------------------------------------------
__global__ void __launch_bounds__(256) k_vreduce(const float* __restrict__ bk) {
    if (blockIdx.x < 4) {
        int d = blockIdx.x * 256 + threadIdx.x;
        float s = 0.f;
#pragma unroll 8
        for (int g = 0; g < N_HCH; g++) s += g_vpart[(size_t)g * D_MODEL + d];
        g_v[d] = s;
    } else {
        __shared__ float red[256];
        float s = 0.f;
        for (int h = threadIdx.x; h < HID; h += 256) s += bk[h] * g_q[h];
        red[threadIdx.x] = s;
        __syncthreads();
        for (int o = 128; o; o >>= 1) {
            if (threadIdx.x < o) red[threadIdx.x] += red[threadIdx.x + o];
            __syncthreads();
        }
        if (threadIdx.x == 0) g_c = red[0];
    }
}

// ---------------------------------------------------------------------------
// Fused scores + per-block top-6 + (last block only) global merge & mean.
// 1024 blocks x 256 threads, 64 rows/block.
// ---------------------------------------------------------------------------
__global__ void __launch_bounds__(256) k_scores_topk(const float* __restrict__ key_mat,
                                                     float* __restrict__ out) {
    __shared__ float sv[D_MODEL];
    __shared__ float ss[ROWS_PER_BLK];
    __shared__ int   isLast;
    __shared__ u64   swarp[8];
    __shared__ u64   swin;
    int tid = threadIdx.x;
    int warp = tid >> 5, lane = tid & 31;

    for (int i = tid; i < D_MODEL; i += 256) sv[i] = g_v[i];
    __syncthreads();

    int rowBase = blockIdx.x * ROWS_PER_BLK;
    const float4* V = reinterpret_cast<const float4*>(sv);
    float c = g_c;

#pragma unroll
    for (int it = 0; it < 8; it++) {
        int r = it * 8 + warp;
        const float4* K = reinterpret_cast<const float4*>(
            key_mat + (size_t)(rowBase + r) * D_MODEL);
        float acc = 0.f;
#pragma unroll
        for (int j = 0; j < 8; j++) {
            float4 k = __ldcs(&K[lane + 32 * j]);
            float4 v = V[lane + 32 * j];
            acc += k.x * v.x + k.y * v.y + k.z * v.z + k.w * v.w;
        }
#pragma unroll
        for (int off = 16; off; off >>= 1)
            acc += __shfl_down_sync(0xffffffffu, acc, off);
        if (lane == 0) ss[r] = acc + c;
    }
    __syncthreads();

    // warp 0: top-6 of 64 scores via bound trick (keys unique; pass t = max < bound)
    if (warp == 0) {
        u64 k0 = make_key(ss[lane],      rowBase + lane);
        u64 k1 = make_key(ss[lane + 32], rowBase + lane + 32);
        u64 bound = ~0ull;
#pragma unroll
        for (int t = 0; t < TOPK; t++) {
            u64 a = (k0 < bound) ? k0 : 0;
            u64 b = (k1 < bound) ? k1 : 0;
            u64 mine = (a > b) ? a : b;
            u64 win  = warp_max_u64(mine);
            if (lane == 0) g_cand[blockIdx.x * TOPK + t] = win;
            bound = win;
        }
    }

    // ---- last-block global merge ----
    __threadfence();
    if (tid == 0) {
        int done = atomicAdd(&g_ctr, 1);
        isLast = (done == SC_BLOCKS - 1);
        if (isLast) g_ctr = 0;                  // reset for next graph replay
    }
    __syncthreads();
    if (!isLast) return;
    __threadfence();                            // acquire-ish: see all g_cand

    u64 bound = ~0ull;
    int topIdx[TOPK];
#pragma unroll
    for (int t = 0; t < TOPK; t++) {
        u64 best = 0;
#pragma unroll
        for (int j = 0; j < CAND_PER_THR; j++) {
            u64 kk = g_cand[tid + 256 * j];
            if (kk < bound && kk > best) best = kk;
        }
        best = warp_max_u64(best);
        if (lane == 0) swarp[warp] = best;
        __syncthreads();
        if (warp == 0) {
            u64 b = (lane < 8) ? swarp[lane] : 0;
            b = warp_max_u64(b);
            if (lane == 0) swin = b;
        }
        __syncthreads();
        bound = swin;
        topIdx[t] = key_idx(bound);
        __syncthreads();
    }

    // mean of the 6 selected rows; 256 threads x 4 columns
#pragma unroll
    for (int j = 0; j < 4; j++) {
        int d = tid + 256 * j;
        float s = 0.f;
#pragma unroll
        for (int t = 0; t < TOPK; t++)
            s += key_mat[(size_t)topIdx[t] * D_MODEL + d];
        out[d] = s * (1.0f / 6.0f);
    }
}

// ---------------------------------------------------------------------------
extern "C" void kernel_launch(void* const* d_in, const int* in_sizes, int n_in,
                              void* d_out, int out_size) {
    const float* query   = (const float*)d_in[0];
    const float* key_mat = (const float*)d_in[1];
    const float* Wq      = (const float*)d_in[2];
    const float* bq      = (const float*)d_in[3];
    const float* Wk      = (const float*)d_in[4];
    const float* bk      = (const float*)d_in[5];
    float* out = (float*)d_out;

    k_qv<<<N_HCH, 256>>>(Wq, query, bq, Wk);
    k_vreduce<<<5, 256>>>(bk);
    k_scores_topk<<<SC_BLOCKS, 256>>>(key_mat, out);
}

// round 8
// speedup vs baseline: 1.3769x; 1.0500x over previous
#include <cuda_runtime.h>

#define D_MODEL 1024
#define HID     4096
#define N_KEYS  65536
#define TOPK    6

#define H_CHUNK 8
#define N_HCH   (HID / H_CHUNK)                // 512 blocks for k_qv

#define ROWS_PER_BLK 64
#define SC_BLOCKS    (N_KEYS / ROWS_PER_BLK)   // 1024
#define N_CAND       (SC_BLOCKS * TOPK)        // 6144
#define CAND_PER_THR (N_CAND / 256)            // 24

typedef unsigned long long u64;

// ---- scratch (no allocation allowed) ----
__device__ float g_q[HID];
__device__ float g_vpart[N_HCH * D_MODEL];
__device__ float g_v[D_MODEL];
__device__ float g_c;
__device__ u64   g_cand[N_CAND];
__device__ int   g_ctr;                        // zero-init; reset by last block

// sortable key: higher key <=> greater value, ties -> lower index wins
__device__ __forceinline__ u64 make_key(float v, int idx) {
    unsigned u = __float_as_uint(v);
    u = (u & 0x80000000u) ? ~u : (u | 0x80000000u);
    return ((u64)u << 32) | (unsigned)(~idx);
}
__device__ __forceinline__ int key_idx(u64 k) { return ~(unsigned)(k & 0xffffffffu); }

__device__ __forceinline__ u64 warp_max_u64(u64 k) {
#pragma unroll
    for (int o = 16; o; o >>= 1) {
        u64 other = __shfl_xor_sync(0xffffffffu, k, o);
        if (other > k) k = other;
    }
    return k;
}

// ---------------------------------------------------------------------------
// Fused: q[h] for this block's 8-row h-chunk (one warp per row), then the
// chunk's partial-v contribution. 512 blocks x 256 threads.
// ---------------------------------------------------------------------------
__global__ void __launch_bounds__(256) k_qv(const float* __restrict__ Wq,
                                            const float* __restrict__ query,
                                            const float* __restrict__ bq,
                                            const float* __restrict__ Wk) {
    __shared__ float sq[D_MODEL];
    __shared__ float sqr[H_CHUNK];
    int tid = threadIdx.x;
    int h0  = blockIdx.x * H_CHUNK;

    for (int i = tid; i < D_MODEL; i += 256) sq[i] = query[i];
    __syncthreads();

    int warp = tid >> 5, lane = tid & 31;
    const float4* Q = reinterpret_cast<const float4*>(sq);
    {
        int h = h0 + warp;                      // 8 warps x 1 row
        const float4* W = reinterpret_cast<const float4*>(Wq + (size_t)h * D_MODEL);
        float acc = 0.f;
#pragma unroll
        for (int j = 0; j < 8; j++) {
            float4 w = __ldcs(&W[lane + 32 * j]);
            float4 q = Q[lane + 32 * j];
            acc += w.x * q.x + w.y * q.y + w.z * q.z + w.w * q.w;
        }
#pragma unroll
        for (int off = 16; off; off >>= 1)
            acc += __shfl_down_sync(0xffffffffu, acc, off);
        if (lane == 0) {
            float qv = acc + bq[h];
            sqr[warp] = qv;
            g_q[h] = qv;
        }
    }
    __syncthreads();

    float acc0 = 0.f, acc1 = 0.f, acc2 = 0.f, acc3 = 0.f;
#pragma unroll
    for (int h = 0; h < H_CHUNK; h++) {
        const float* row = Wk + (size_t)(h0 + h) * D_MODEL;
        float qh = sqr[h];
        acc0 += __ldcs(&row[tid      ]) * qh;
        acc1 += __ldcs(&row[tid + 256]) * qh;
        acc2 += __ldcs(&row[tid + 512]) * qh;
        acc3 += __ldcs(&row[tid + 768]) * qh;
    }
    float* vp = g_vpart + (size_t)blockIdx.x * D_MODEL;
    vp[tid      ] = acc0;
    vp[tid + 256] = acc1;
    vp[tid + 512] = acc2;
    vp[tid + 768] = acc3;
}

// ---------------------------------------------------------------------------
// reduce 512 partials -> v (16 blocks x 64 d's x 4 group-slices);
// block 16 computes c = bk . q. Fixed summation order -> deterministic.
// ---------------------------------------------------------------------------
__global__ void __launch_bounds__(256) k_vreduce(const float* __restrict__ bk) {
    __shared__ float red[256];
    int tid = threadIdx.x;

    if (blockIdx.x < 16) {
        int dloc  = tid & 63;                   // 0..63
        int slice = tid >> 6;                   // 0..3
        int d     = blockIdx.x * 64 + dloc;
        float s = 0.f;
        int g0 = slice * (N_HCH / 4);
#pragma unroll 8
        for (int g = 0; g < N_HCH / 4; g++)
            s += g_vpart[(size_t)(g0 + g) * D_MODEL + d];
        red[tid] = s;
        __syncthreads();
        if (tid < 64)
            g_v[d] = red[tid] + red[tid + 64] + red[tid + 128] + red[tid + 192];
    } else {
        float s = 0.f;
        for (int h = tid; h < HID; h += 256) s += bk[h] * g_q[h];
        red[tid] = s;
        __syncthreads();
        for (int o = 128; o; o >>= 1) {
            if (tid < o) red[tid] += red[tid + o];
            __syncthreads();
        }
        if (tid == 0) g_c = red[0];
    }
}

// ---------------------------------------------------------------------------
// Fused scores + per-block top-6 + (last block only) global merge & mean.
// 1024 blocks x 256 threads, 64 rows/block.
// ---------------------------------------------------------------------------
__global__ void __launch_bounds__(256) k_scores_topk(const float* __restrict__ key_mat,
                                                     float* __restrict__ out) {
    __shared__ float sv[D_MODEL];
    __shared__ float ss[ROWS_PER_BLK];
    __shared__ int   isLast;
    __shared__ u64   swarp[8];
    __shared__ u64   swin;
    int tid = threadIdx.x;
    int warp = tid >> 5, lane = tid & 31;

    for (int i = tid; i < D_MODEL; i += 256) sv[i] = g_v[i];
    __syncthreads();

    int rowBase = blockIdx.x * ROWS_PER_BLK;
    const float4* V = reinterpret_cast<const float4*>(sv);
    float c = g_c;

#pragma unroll
    for (int it = 0; it < 8; it++) {
        int r = it * 8 + warp;
        const float4* K = reinterpret_cast<const float4*>(
            key_mat + (size_t)(rowBase + r) * D_MODEL);
        float acc = 0.f;
#pragma unroll
        for (int j = 0; j < 8; j++) {
            float4 k = __ldcs(&K[lane + 32 * j]);
            float4 v = V[lane + 32 * j];
            acc += k.x * v.x + k.y * v.y + k.z * v.z + k.w * v.w;
        }
#pragma unroll
        for (int off = 16; off; off >>= 1)
            acc += __shfl_down_sync(0xffffffffu, acc, off);
        if (lane == 0) ss[r] = acc + c;
    }
    __syncthreads();

    // warp 0: top-6 of 64 scores via bound trick (keys unique; pass t = max < bound)
    if (warp == 0) {
        u64 k0 = make_key(ss[lane],      rowBase + lane);
        u64 k1 = make_key(ss[lane + 32], rowBase + lane + 32);
        u64 bound = ~0ull;
#pragma unroll
        for (int t = 0; t < TOPK; t++) {
            u64 a = (k0 < bound) ? k0 : 0;
            u64 b = (k1 < bound) ? k1 : 0;
            u64 mine = (a > b) ? a : b;
            u64 win  = warp_max_u64(mine);
            if (lane == 0) g_cand[blockIdx.x * TOPK + t] = win;
            bound = win;
        }
    }

    // ---- last-block global merge ----
    __threadfence();
    if (tid == 0) {
        int done = atomicAdd(&g_ctr, 1);
        isLast = (done == SC_BLOCKS - 1);
        if (isLast) g_ctr = 0;                  // reset for next graph replay
    }
    __syncthreads();
    if (!isLast) return;
    __threadfence();                            // see all g_cand

    u64 bound = ~0ull;
    int topIdx[TOPK];
#pragma unroll
    for (int t = 0; t < TOPK; t++) {
        u64 best = 0;
#pragma unroll
        for (int j = 0; j < CAND_PER_THR; j++) {
            u64 kk = g_cand[tid + 256 * j];
            if (kk < bound && kk > best) best = kk;
        }
        best = warp_max_u64(best);
        if (lane == 0) swarp[warp] = best;
        __syncthreads();
        if (warp == 0) {
            u64 b = (lane < 8) ? swarp[lane] : 0;
            b = warp_max_u64(b);
            if (lane == 0) swin = b;
        }
        __syncthreads();
        bound = swin;
        topIdx[t] = key_idx(bound);
        __syncthreads();
    }

    // mean of the 6 selected rows; 256 threads x 4 columns
#pragma unroll
    for (int j = 0; j < 4; j++) {
        int d = tid + 256 * j;
        float s = 0.f;
#pragma unroll
        for (int t = 0; t < TOPK; t++)
            s += key_mat[(size_t)topIdx[t] * D_MODEL + d];
        out[d] = s * (1.0f / 6.0f);
    }
}

// ---------------------------------------------------------------------------
extern "C" void kernel_launch(void* const* d_in, const int* in_sizes, int n_in,
                              void* d_out, int out_size) {
    const float* query   = (const float*)d_in[0];
    const float* key_mat = (const float*)d_in[1];
    const float* Wq      = (const float*)d_in[2];
    const float* bq      = (const float*)d_in[3];
    const float* Wk      = (const float*)d_in[4];
    const float* bk      = (const float*)d_in[5];
    float* out = (float*)d_out;

    k_qv<<<N_HCH, 256>>>(Wq, query, bq, Wk);
    k_vreduce<<<17, 256>>>(bk);
    k_scores_topk<<<SC_BLOCKS, 256>>>(key_mat, out);
}

// round 9
// speedup vs baseline: 1.3855x; 1.0063x over previous
#include <cuda_runtime.h>

#define D_MODEL 1024
#define HID     4096
#define N_KEYS  65536
#define TOPK    6

#define H_CHUNK 8
#define N_HCH   (HID / H_CHUNK)                // 512 blocks for k_qv

#define ROWS_PER_BLK 64
#define SC_BLOCKS    (N_KEYS / ROWS_PER_BLK)   // 1024
#define N_CAND       (SC_BLOCKS * TOPK)        // 6144
#define CAND_PER_THR (N_CAND / 256)            // 24

typedef unsigned long long u64;

// ---- scratch (no allocation allowed) ----
__device__ float g_q[HID];
__device__ float g_vpart[N_HCH * D_MODEL];
__device__ float g_v[D_MODEL];
__device__ float g_c;
__device__ u64   g_cand[N_CAND];
__device__ int   g_ctr;                        // zero-init; reset by last block

// sortable key: higher key <=> greater value, ties -> lower index wins
__device__ __forceinline__ u64 make_key(float v, int idx) {
    unsigned u = __float_as_uint(v);
    u = (u & 0x80000000u) ? ~u : (u | 0x80000000u);
    return ((u64)u << 32) | (unsigned)(~idx);
}
__device__ __forceinline__ int key_idx(u64 k) { return ~(unsigned)(k & 0xffffffffu); }

__device__ __forceinline__ u64 warp_max_u64(u64 k) {
#pragma unroll
    for (int o = 16; o; o >>= 1) {
        u64 other = __shfl_xor_sync(0xffffffffu, k, o);
        if (other > k) k = other;
    }
    return k;
}

// ---------------------------------------------------------------------------
// Fused: q[h] for this block's 8-row h-chunk (one warp per row), then the
// chunk's partial-v contribution. 512 blocks x 256 threads.
// ---------------------------------------------------------------------------
__global__ void __launch_bounds__(256) k_qv(const float* __restrict__ Wq,
                                            const float* __restrict__ query,
                                            const float* __restrict__ bq,
                                            const float* __restrict__ Wk) {
    __shared__ float sq[D_MODEL];
    __shared__ float sqr[H_CHUNK];
    int tid = threadIdx.x;
    int h0  = blockIdx.x * H_CHUNK;

    for (int i = tid; i < D_MODEL; i += 256) sq[i] = query[i];
    __syncthreads();

    int warp = tid >> 5, lane = tid & 31;
    const float4* Q = reinterpret_cast<const float4*>(sq);
    {
        int h = h0 + warp;                      // 8 warps x 1 row
        const float4* W = reinterpret_cast<const float4*>(Wq + (size_t)h * D_MODEL);
        float acc = 0.f;
#pragma unroll
        for (int j = 0; j < 8; j++) {
            float4 w = __ldcs(&W[lane + 32 * j]);
            float4 q = Q[lane + 32 * j];
            acc += w.x * q.x + w.y * q.y + w.z * q.z + w.w * q.w;
        }
#pragma unroll
        for (int off = 16; off; off >>= 1)
            acc += __shfl_down_sync(0xffffffffu, acc, off);
        if (lane == 0) {
            float qv = acc + bq[h];
            sqr[warp] = qv;
            g_q[h] = qv;
        }
    }
    __syncthreads();

    float acc0 = 0.f, acc1 = 0.f, acc2 = 0.f, acc3 = 0.f;
#pragma unroll
    for (int h = 0; h < H_CHUNK; h++) {
        const float* row = Wk + (size_t)(h0 + h) * D_MODEL;
        float qh = sqr[h];
        acc0 += __ldcs(&row[tid      ]) * qh;
        acc1 += __ldcs(&row[tid + 256]) * qh;
        acc2 += __ldcs(&row[tid + 512]) * qh;
        acc3 += __ldcs(&row[tid + 768]) * qh;
    }
    float* vp = g_vpart + (size_t)blockIdx.x * D_MODEL;
    vp[tid      ] = acc0;
    vp[tid + 256] = acc1;
    vp[tid + 512] = acc2;
    vp[tid + 768] = acc3;
}

// ---------------------------------------------------------------------------
// reduce 512 partials -> v (16 blocks x 64 d's x 4 group-slices);
// block 16 computes c = bk . q. Fixed summation order -> deterministic.
// ---------------------------------------------------------------------------
__global__ void __launch_bounds__(256) k_vreduce(const float* __restrict__ bk) {
    __shared__ float red[256];
    int tid = threadIdx.x;

    if (blockIdx.x < 16) {
        int dloc  = tid & 63;                   // 0..63
        int slice = tid >> 6;                   // 0..3
        int d     = blockIdx.x * 64 + dloc;
        float s = 0.f;
        int g0 = slice * (N_HCH / 4);
#pragma unroll 8
        for (int g = 0; g < N_HCH / 4; g++)
            s += g_vpart[(size_t)(g0 + g) * D_MODEL + d];
        red[tid] = s;
        __syncthreads();
        if (tid < 64)
            g_v[d] = red[tid] + red[tid + 64] + red[tid + 128] + red[tid + 192];
    } else {
        float s = 0.f;
        for (int h = tid; h < HID; h += 256) s += bk[h] * g_q[h];
        red[tid] = s;
        __syncthreads();
        for (int o = 128; o; o >>= 1) {
            if (tid < o) red[tid] += red[tid + o];
            __syncthreads();
        }
        if (tid == 0) g_c = red[0];
    }
}

// ---------------------------------------------------------------------------
// Fused scores + per-block top-6 + (last block only) global merge & mean.
// 1024 blocks x 256 threads, 64 rows/block.
// ---------------------------------------------------------------------------
__global__ void __launch_bounds__(256) k_scores_topk(const float* __restrict__ key_mat,
                                                     float* __restrict__ out) {
    __shared__ float sv[D_MODEL];
    __shared__ float ss[ROWS_PER_BLK];
    __shared__ int   isLast;
    __shared__ u64   swarp[8];
    __shared__ u64   swin;
    int tid = threadIdx.x;
    int warp = tid >> 5, lane = tid & 31;

    for (int i = tid; i < D_MODEL; i += 256) sv[i] = g_v[i];
    __syncthreads();

    int rowBase = blockIdx.x * ROWS_PER_BLK;
    const float4* V = reinterpret_cast<const float4*>(sv);
    float c = g_c;

#pragma unroll
    for (int it = 0; it < 8; it++) {
        int r = it * 8 + warp;
        const float4* K = reinterpret_cast<const float4*>(
            key_mat + (size_t)(rowBase + r) * D_MODEL);
        float acc = 0.f;
#pragma unroll
        for (int j = 0; j < 8; j++) {
            float4 k = __ldcs(&K[lane + 32 * j]);
            float4 v = V[lane + 32 * j];
            acc += k.x * v.x + k.y * v.y + k.z * v.z + k.w * v.w;
        }
#pragma unroll
        for (int off = 16; off; off >>= 1)
            acc += __shfl_down_sync(0xffffffffu, acc, off);
        if (lane == 0) ss[r] = acc + c;
    }
    __syncthreads();

    // warp 0: top-6 of 64 scores via bound trick (keys unique; pass t = max < bound)
    if (warp == 0) {
        u64 k0 = make_key(ss[lane],      rowBase + lane);
        u64 k1 = make_key(ss[lane + 32], rowBase + lane + 32);
        u64 bound = ~0ull;
#pragma unroll
        for (int t = 0; t < TOPK; t++) {
            u64 a = (k0 < bound) ? k0 : 0;
            u64 b = (k1 < bound) ? k1 : 0;
            u64 mine = (a > b) ? a : b;
            u64 win  = warp_max_u64(mine);
            if (lane == 0) g_cand[blockIdx.x * TOPK + t] = win;
            bound = win;
        }
    }

    // ---- last-block global merge ----
    __threadfence();
    if (tid == 0) {
        int done = atomicAdd(&g_ctr, 1);
        isLast = (done == SC_BLOCKS - 1);
        if (isLast) g_ctr = 0;                  // reset for next graph replay
    }
    __syncthreads();
    if (!isLast) return;
    __threadfence();                            // see all g_cand

    u64 bound = ~0ull;
    int topIdx[TOPK];
#pragma unroll
    for (int t = 0; t < TOPK; t++) {
        u64 best = 0;
#pragma unroll
        for (int j = 0; j < CAND_PER_THR; j++) {
            u64 kk = g_cand[tid + 256 * j];
            if (kk < bound && kk > best) best = kk;
        }
        best = warp_max_u64(best);
        if (lane == 0) swarp[warp] = best;
        __syncthreads();
        if (warp == 0) {
            u64 b = (lane < 8) ? swarp[lane] : 0;
            b = warp_max_u64(b);
            if (lane == 0) swin = b;
        }
        __syncthreads();
        bound = swin;
        topIdx[t] = key_idx(bound);
        __syncthreads();
    }

    // mean of the 6 selected rows; 256 threads x 4 columns
#pragma unroll
    for (int j = 0; j < 4; j++) {
        int d = tid + 256 * j;
        float s = 0.f;
#pragma unroll
        for (int t = 0; t < TOPK; t++)
            s += key_mat[(size_t)topIdx[t] * D_MODEL + d];
        out[d] = s * (1.0f / 6.0f);
    }
}

// ---------------------------------------------------------------------------
extern "C" void kernel_launch(void* const* d_in, const int* in_sizes, int n_in,
                              void* d_out, int out_size) {
    const float* query   = (const float*)d_in[0];
    const float* key_mat = (const float*)d_in[1];
    const float* Wq      = (const float*)d_in[2];
    const float* bq      = (const float*)d_in[3];
    const float* Wk      = (const float*)d_in[4];
    const float* bk      = (const float*)d_in[5];
    float* out = (float*)d_out;

    k_qv<<<N_HCH, 256>>>(Wq, query, bq, Wk);
    k_vreduce<<<17, 256>>>(bk);
    k_scores_topk<<<SC_BLOCKS, 256>>>(key_mat, out);
}